// round 3
// baseline (speedup 1.0000x reference)
#include <cuda_runtime.h>
#include <math.h>

#define N_NODES 50000
#define N_EDGES 1600000
#define HIDDIM 128
#define NFEAT 128
#define NGAUSS 64

// Scratch (static device globals; allocation-free)
__device__ float g_h[(size_t)N_NODES * NFEAT];
__device__ float g_agg[(size_t)N_NODES * NFEAT];
__device__ float g_tmp[(size_t)N_NODES * HIDDIM];

__device__ __forceinline__ float sspf(float v) {
    // softplus(v) - log(2), numerically stable (matches jnp.logaddexp(v,0)-log2)
    return fmaxf(v, 0.0f) + log1pf(expf(-fabsf(v))) - 0.69314718055994531f;
}

__device__ __forceinline__ int rowof(int r0, int i) {
    return (i < 4) ? (r0 + i) : (64 + r0 + i - 4);
}

// ---------------------------------------------------------------------------
// Generic 128-wide GEMM: out[M,128] = act(A[M,128] @ W[128,128] + bias)
// ACT: 0 = none, 1 = shifted softplus. BIAS: 0/1.
// blockDim = 256, one 128-row tile per block.
// ---------------------------------------------------------------------------
template <int ACT, int BIAS>
__global__ void gemm128_kernel(const float* __restrict__ A,
                               const float* __restrict__ W,
                               const float* __restrict__ bias,
                               float* __restrict__ out, int M) {
    extern __shared__ float sm[];
    float* As = sm;                  // 128*128
    float* Ws = sm + 128 * 128;      // 128*128
    float* bs = Ws + 128 * 128;      // 128

    const int t = threadIdx.x;
    const int row0 = blockIdx.x * 128;

    // Load W and bias into smem
    {
        const float4* Wg = (const float4*)W;
        float4* Wsh = (float4*)Ws;
        for (int i = t; i < 128 * 128 / 4; i += 256) Wsh[i] = Wg[i];
        if (t < 128) bs[t] = BIAS ? bias[t] : 0.0f;
    }
    // Load A tile (row-major, guard tail rows)
    {
        float4* Ash = (float4*)As;
        for (int i = t; i < 128 * 32; i += 256) {
            int r = i >> 5, c = i & 31;
            int rg = row0 + r;
            float4 v = make_float4(0.f, 0.f, 0.f, 0.f);
            if (rg < M) v = ((const float4*)(A + (size_t)rg * 128))[c];
            Ash[(r << 5) + c] = v;
        }
    }
    __syncthreads();

    const int tx = t & 15, ty = t >> 4;
    const int r0 = ty * 4, c0 = tx * 4;

    float acc[8][8];
#pragma unroll
    for (int i = 0; i < 8; i++) {
#pragma unroll
        for (int j = 0; j < 4; j++) {
            acc[i][j] = bs[c0 + j];
            acc[i][4 + j] = bs[64 + c0 + j];
        }
    }

#pragma unroll 4
    for (int k = 0; k < 128; k++) {
        float a[8];
#pragma unroll
        for (int i = 0; i < 4; i++) {
            a[i] = As[(r0 + i) * 128 + k];
            a[4 + i] = As[(64 + r0 + i) * 128 + k];
        }
        float4 bq0 = *(const float4*)(Ws + k * 128 + c0);
        float4 bq1 = *(const float4*)(Ws + k * 128 + 64 + c0);
        float b[8] = {bq0.x, bq0.y, bq0.z, bq0.w, bq1.x, bq1.y, bq1.z, bq1.w};
#pragma unroll
        for (int i = 0; i < 8; i++)
#pragma unroll
            for (int j = 0; j < 8; j++) acc[i][j] = fmaf(a[i], b[j], acc[i][j]);
    }

    // Epilogue
#pragma unroll
    for (int i = 0; i < 8; i++) {
        int rg = row0 + rowof(r0, i);
        if (rg >= M) continue;
        float v[8];
#pragma unroll
        for (int j = 0; j < 8; j++) {
            float x = acc[i][j];
            v[j] = (ACT == 1) ? sspf(x) : x;
        }
        float4 s0 = make_float4(v[0], v[1], v[2], v[3]);
        float4 s1 = make_float4(v[4], v[5], v[6], v[7]);
        *(float4*)(out + (size_t)rg * 128 + c0) = s0;
        *(float4*)(out + (size_t)rg * 128 + 64 + c0) = s1;
    }
}

// ---------------------------------------------------------------------------
// Fused per-edge kernel: W = ssp(EA@W1+b1)@W2+b2; W *= C(len);
// msg = h[src] * W; atomicAdd into g_agg[dst].
// Persistent blocks; weights cached in smem once per block.
// blockDim = 256, tile = 128 edges.
// ---------------------------------------------------------------------------
__global__ void edge_fused_kernel(const float* __restrict__ edge_attr,
                                  const int* __restrict__ eidx,
                                  const float* __restrict__ elen,
                                  const float* __restrict__ w1,
                                  const float* __restrict__ b1,
                                  const float* __restrict__ w2,
                                  const float* __restrict__ b2) {
    extern __shared__ float sm[];
    float* w1s = sm;                   // 64*128  = 8192
    float* w2s = w1s + 64 * 128;       // 128*128 = 16384
    float* eas = w2s + 128 * 128;      // 128*64  = 8192
    float* ts = eas + 128 * 64;        // 128*128 = 16384
    float* b1s = ts + 128 * 128;       // 128
    float* b2s = b1s + 128;            // 128
    float* Cs = b2s + 128;             // 128
    int* ss = (int*)(Cs + 128);        // 128
    int* ds = ss + 128;                // 128

    const int t = threadIdx.x;
    const int tx = t & 15, ty = t >> 4;
    const int r0 = ty * 4, c0 = tx * 4;
    const int* srcp = eidx;
    const int* dstp = eidx + N_EDGES;

    // Cache weights once per block
    for (int i = t; i < 64 * 128 / 4; i += 256)
        ((float4*)w1s)[i] = ((const float4*)w1)[i];
    for (int i = t; i < 128 * 128 / 4; i += 256)
        ((float4*)w2s)[i] = ((const float4*)w2)[i];
    if (t < 128) {
        b1s[t] = b1[t];
        b2s[t] = b2[t];
    }

    const int ntiles = N_EDGES / 128;  // 12500, exact
    for (int tile = blockIdx.x; tile < ntiles; tile += gridDim.x) {
        const int e0 = tile * 128;
        __syncthreads();  // protect Cs/ss/ds/eas against prior-iteration readers

        // Load edge_attr tile [128][64]
        for (int i = t; i < 128 * 16; i += 256) {
            int r = i >> 4, c = i & 15;
            ((float4*)(eas + r * 64))[c] =
                ((const float4*)(edge_attr + (size_t)(e0 + r) * 64))[c];
        }
        if (t < 128) {
            int e = e0 + t;
            ss[t] = srcp[e];
            ds[t] = dstp[e];
            float l = elen[e];
            float c = 0.5f * (cosf(l * 0.31415926535897932f) + 1.0f);
            if (!(l <= 10.0f && l >= 0.0f)) c = 0.0f;
            Cs[t] = c;
        }
        __syncthreads();

        // ---- Stage 1: t = ssp(EA @ W1 + b1), K = 64 ----
        float acc[8][8];
#pragma unroll
        for (int i = 0; i < 8; i++) {
#pragma unroll
            for (int j = 0; j < 4; j++) {
                acc[i][j] = b1s[c0 + j];
                acc[i][4 + j] = b1s[64 + c0 + j];
            }
        }
#pragma unroll 4
        for (int k = 0; k < 64; k++) {
            float a[8];
#pragma unroll
            for (int i = 0; i < 4; i++) {
                a[i] = eas[(r0 + i) * 64 + k];
                a[4 + i] = eas[(64 + r0 + i) * 64 + k];
            }
            float4 bq0 = *(const float4*)(w1s + k * 128 + c0);
            float4 bq1 = *(const float4*)(w1s + k * 128 + 64 + c0);
            float b[8] = {bq0.x, bq0.y, bq0.z, bq0.w, bq1.x, bq1.y, bq1.z, bq1.w};
#pragma unroll
            for (int i = 0; i < 8; i++)
#pragma unroll
                for (int j = 0; j < 8; j++)
                    acc[i][j] = fmaf(a[i], b[j], acc[i][j]);
        }
        // ssp and stash into ts[edge][feat]
#pragma unroll
        for (int i = 0; i < 8; i++) {
            int r = rowof(r0, i);
            float4 s0 = make_float4(sspf(acc[i][0]), sspf(acc[i][1]),
                                    sspf(acc[i][2]), sspf(acc[i][3]));
            float4 s1 = make_float4(sspf(acc[i][4]), sspf(acc[i][5]),
                                    sspf(acc[i][6]), sspf(acc[i][7]));
            *(float4*)(ts + r * 128 + c0) = s0;
            *(float4*)(ts + r * 128 + 64 + c0) = s1;
        }
        __syncthreads();

        // ---- Stage 2: W = t @ W2 + b2, K = 128 ----
#pragma unroll
        for (int i = 0; i < 8; i++) {
#pragma unroll
            for (int j = 0; j < 4; j++) {
                acc[i][j] = b2s[c0 + j];
                acc[i][4 + j] = b2s[64 + c0 + j];
            }
        }
#pragma unroll 4
        for (int k = 0; k < 128; k++) {
            float a[8];
#pragma unroll
            for (int i = 0; i < 4; i++) {
                a[i] = ts[(r0 + i) * 128 + k];
                a[4 + i] = ts[(64 + r0 + i) * 128 + k];
            }
            float4 bq0 = *(const float4*)(w2s + k * 128 + c0);
            float4 bq1 = *(const float4*)(w2s + k * 128 + 64 + c0);
            float b[8] = {bq0.x, bq0.y, bq0.z, bq0.w, bq1.x, bq1.y, bq1.z, bq1.w};
#pragma unroll
            for (int i = 0; i < 8; i++)
#pragma unroll
                for (int j = 0; j < 8; j++)
                    acc[i][j] = fmaf(a[i], b[j], acc[i][j]);
        }

        // ---- Epilogue: envelope * gather(h[src]) -> scatter-add agg[dst] ----
#pragma unroll
        for (int i = 0; i < 8; i++) {
            int r = rowof(r0, i);
            float Ce = Cs[r];
            const float* hrow = g_h + (size_t)ss[r] * 128;
            float* arow = g_agg + (size_t)ds[r] * 128;
            float4 h0 = *(const float4*)(hrow + c0);
            float4 h1 = *(const float4*)(hrow + 64 + c0);
            atomicAdd(arow + c0 + 0, acc[i][0] * Ce * h0.x);
            atomicAdd(arow + c0 + 1, acc[i][1] * Ce * h0.y);
            atomicAdd(arow + c0 + 2, acc[i][2] * Ce * h0.z);
            atomicAdd(arow + c0 + 3, acc[i][3] * Ce * h0.w);
            atomicAdd(arow + 64 + c0 + 0, acc[i][4] * Ce * h1.x);
            atomicAdd(arow + 64 + c0 + 1, acc[i][5] * Ce * h1.y);
            atomicAdd(arow + 64 + c0 + 2, acc[i][6] * Ce * h1.z);
            atomicAdd(arow + 64 + c0 + 3, acc[i][7] * Ce * h1.w);
        }
    }
}

__global__ void zero_kernel(float4* p, int n4) {
    int i = blockIdx.x * blockDim.x + threadIdx.x;
    if (i < n4) p[i] = make_float4(0.f, 0.f, 0.f, 0.f);
}

extern "C" void kernel_launch(void* const* d_in, const int* in_sizes, int n_in,
                              void* d_out, int out_size) {
    const float* x = (const float*)d_in[0];
    const int* eidx = (const int*)d_in[1];
    const float* elen = (const float*)d_in[2];
    const float* eattr = (const float*)d_in[3];
    const float* lin1_w = (const float*)d_in[4];
    const float* nn_w1 = (const float*)d_in[5];
    const float* nn_b1 = (const float*)d_in[6];
    const float* nn_w2 = (const float*)d_in[7];
    const float* nn_b2 = (const float*)d_in[8];
    const float* lin2_w = (const float*)d_in[9];
    const float* lin2_b = (const float*)d_in[10];
    const float* lin_w = (const float*)d_in[11];
    const float* lin_b = (const float*)d_in[12];
    float* out = (float*)d_out;

    float *h_p, *agg_p, *tmp_p;
    cudaGetSymbolAddress((void**)&h_p, g_h);
    cudaGetSymbolAddress((void**)&agg_p, g_agg);
    cudaGetSymbolAddress((void**)&tmp_p, g_tmp);

    const size_t gemm_smem = (size_t)(2 * 128 * 128 + 128) * sizeof(float);
    const size_t edge_smem =
        (size_t)(64 * 128 + 128 * 128 + 128 * 64 + 128 * 128 + 3 * 128) *
            sizeof(float) +
        2 * 128 * sizeof(int);

    cudaFuncSetAttribute(gemm128_kernel<0, 0>,
                         cudaFuncAttributeMaxDynamicSharedMemorySize,
                         (int)gemm_smem);
    cudaFuncSetAttribute(gemm128_kernel<1, 1>,
                         cudaFuncAttributeMaxDynamicSharedMemorySize,
                         (int)gemm_smem);
    cudaFuncSetAttribute(gemm128_kernel<0, 1>,
                         cudaFuncAttributeMaxDynamicSharedMemorySize,
                         (int)gemm_smem);
    cudaFuncSetAttribute(edge_fused_kernel,
                         cudaFuncAttributeMaxDynamicSharedMemorySize,
                         (int)edge_smem);

    const int gridN = (N_NODES + 127) / 128;  // 391

    // 1) h = x @ lin1_w
    gemm128_kernel<0, 0><<<gridN, 256, gemm_smem>>>(x, lin1_w, nullptr, h_p,
                                                    N_NODES);
    // 2) agg = 0
    {
        int n4 = N_NODES * NFEAT / 4;
        zero_kernel<<<(n4 + 255) / 256, 256>>>((float4*)agg_p, n4);
    }
    // 3) fused edge MLP + envelope + gather/scatter
    edge_fused_kernel<<<1184, 256, edge_smem>>>(eattr, eidx, elen, nn_w1, nn_b1,
                                                nn_w2, nn_b2);
    // 4) tmp = ssp(agg @ lin2_w + lin2_b)
    gemm128_kernel<1, 1><<<gridN, 256, gemm_smem>>>(agg_p, lin2_w, lin2_b,
                                                    tmp_p, N_NODES);
    // 5) out = tmp @ lin_w + lin_b
    gemm128_kernel<0, 1><<<gridN, 256, gemm_smem>>>(tmp_p, lin_w, lin_b, out,
                                                    N_NODES);
}

// round 6
// speedup vs baseline: 1.8468x; 1.8468x over previous
#include <cuda_runtime.h>
#include <math.h>
#include <stdint.h>

#define N_NODES 50000
#define N_EDGES 1600000
#define HIDDIM 128
#define NFEAT 128
#define NGAUSS 64

// Scratch (static device globals; allocation-free)
__device__ float g_h[(size_t)N_NODES * NFEAT];
__device__ float g_agg[(size_t)N_NODES * NFEAT];
__device__ float g_tmp[(size_t)N_NODES * HIDDIM];

__device__ __forceinline__ float sspf(float v) {
    // softplus(v) - log(2), numerically stable
    return fmaxf(v, 0.0f) + log1pf(expf(-fabsf(v))) - 0.69314718055994531f;
}

__device__ __forceinline__ uint32_t f2tf32(float f) {
    uint32_t r;
    asm("cvt.rna.tf32.f32 %0, %1;" : "=r"(r) : "f"(f));
    return r;
}

__device__ __forceinline__ void mma_tf32(float d[4], const uint32_t a[4],
                                         uint32_t b0, uint32_t b1) {
    asm volatile(
        "mma.sync.aligned.m16n8k8.row.col.f32.tf32.tf32.f32 "
        "{%0,%1,%2,%3}, {%4,%5,%6,%7}, {%8,%9}, {%0,%1,%2,%3};"
        : "+f"(d[0]), "+f"(d[1]), "+f"(d[2]), "+f"(d[3])
        : "r"(a[0]), "r"(a[1]), "r"(a[2]), "r"(a[3]), "r"(b0), "r"(b1));
}

__device__ __forceinline__ void red2(float* p, float v0, float v1) {
    asm volatile("red.global.add.v2.f32 [%0], {%1, %2};" ::"l"(p), "f"(v0),
                 "f"(v1)
                 : "memory");
}

__device__ __forceinline__ int rowof(int r0, int i) {
    return (i < 4) ? (r0 + i) : (64 + r0 + i - 4);
}

// ---------------------------------------------------------------------------
// Node GEMM (fp32 FFMA): out[M,128] = act(A[M,128] @ W[128,128] + bias)
// ---------------------------------------------------------------------------
template <int ACT, int BIAS>
__global__ void gemm128_kernel(const float* __restrict__ A,
                               const float* __restrict__ W,
                               const float* __restrict__ bias,
                               float* __restrict__ out, int M) {
    extern __shared__ float sm[];
    float* As = sm;
    float* Ws = sm + 128 * 128;
    float* bs = Ws + 128 * 128;

    const int t = threadIdx.x;
    const int row0 = blockIdx.x * 128;

    {
        const float4* Wg = (const float4*)W;
        float4* Wsh = (float4*)Ws;
        for (int i = t; i < 128 * 128 / 4; i += 256) Wsh[i] = Wg[i];
        if (t < 128) bs[t] = BIAS ? bias[t] : 0.0f;
    }
    {
        float4* Ash = (float4*)As;
        for (int i = t; i < 128 * 32; i += 256) {
            int r = i >> 5, c = i & 31;
            int rg = row0 + r;
            float4 v = make_float4(0.f, 0.f, 0.f, 0.f);
            if (rg < M) v = ((const float4*)(A + (size_t)rg * 128))[c];
            Ash[(r << 5) + c] = v;
        }
    }
    __syncthreads();

    const int tx = t & 15, ty = t >> 4;
    const int r0 = ty * 4, c0 = tx * 4;

    float acc[8][8];
#pragma unroll
    for (int i = 0; i < 8; i++)
#pragma unroll
        for (int j = 0; j < 4; j++) {
            acc[i][j] = bs[c0 + j];
            acc[i][4 + j] = bs[64 + c0 + j];
        }

#pragma unroll 4
    for (int k = 0; k < 128; k++) {
        float a[8];
#pragma unroll
        for (int i = 0; i < 4; i++) {
            a[i] = As[(r0 + i) * 128 + k];
            a[4 + i] = As[(64 + r0 + i) * 128 + k];
        }
        float4 bq0 = *(const float4*)(Ws + k * 128 + c0);
        float4 bq1 = *(const float4*)(Ws + k * 128 + 64 + c0);
        float b[8] = {bq0.x, bq0.y, bq0.z, bq0.w, bq1.x, bq1.y, bq1.z, bq1.w};
#pragma unroll
        for (int i = 0; i < 8; i++)
#pragma unroll
            for (int j = 0; j < 8; j++) acc[i][j] = fmaf(a[i], b[j], acc[i][j]);
    }

#pragma unroll
    for (int i = 0; i < 8; i++) {
        int rg = row0 + rowof(r0, i);
        if (rg >= M) continue;
        float v[8];
#pragma unroll
        for (int j = 0; j < 8; j++) {
            float x = acc[i][j];
            v[j] = (ACT == 1) ? sspf(x) : x;
        }
        *(float4*)(out + (size_t)rg * 128 + c0) =
            make_float4(v[0], v[1], v[2], v[3]);
        *(float4*)(out + (size_t)rg * 128 + 64 + c0) =
            make_float4(v[4], v[5], v[6], v[7]);
    }
}

// ---------------------------------------------------------------------------
// Fused edge kernel, tf32 tensor-core version.
// Tile = 128 edges x 128 feats. 256 threads = 8 warps (4 row-groups x 2 col-
// groups; warp tile 32x64 = 2 mtiles x 8 ntiles of m16n8k8).
// smem strides chosen for conflict-free fragment loads:
//   A-tiles (EAs/ts): stride % 32 == 4  -> bank = 4*gid + tid4 (unique)
//   W-tiles (W1s/W2s): stride % 32 == 8 -> bank = 8*tid4 + gid (unique)
// ---------------------------------------------------------------------------
#define LDA_EA 68
#define LDA_TS 132
#define LDW 136

__global__ __launch_bounds__(256, 1) void edge_fused_kernel(
    const float* __restrict__ edge_attr, const int* __restrict__ eidx,
    const float* __restrict__ elen, const float* __restrict__ w1,
    const float* __restrict__ b1, const float* __restrict__ w2,
    const float* __restrict__ b2) {
    extern __shared__ uint32_t smu[];
    uint32_t* EAs = smu;                       // 128 * 68  = 8704
    uint32_t* W1s = EAs + 128 * LDA_EA;        // 64 * 136  = 8704
    uint32_t* W2s = W1s + 64 * LDW;            // 128 * 136 = 17408
    uint32_t* tss = W2s + 128 * LDW;           // 128 * 132 = 16896
    float* b1s = (float*)(tss + 128 * LDA_TS); // 128
    float* b2s = b1s + 128;                    // 128
    float* Cs = b2s + 128;                     // 128
    int* ss = (int*)(Cs + 128);                // 128
    int* ds = ss + 128;                        // 128

    const int t = threadIdx.x;
    const int lane = t & 31, warp = t >> 5;
    const int gid = lane >> 2, tid4 = lane & 3;
    const int rg = warp & 3, cg = warp >> 1 >> 1;  // warp>>2
    const int r0 = rg * 32, n0c = cg * 64;
    const int* srcp = eidx;
    const int* dstp = eidx + N_EDGES;

    // ---- One-time: weights -> smem (converted to tf32) ----
    for (int i = t; i < 64 * 32; i += 256) {  // W1: 64x128 in float4s
        int r = i >> 5, c4 = i & 31;
        float4 v = ((const float4*)(w1 + (size_t)r * 128))[c4];
        uint32_t* dstw = W1s + r * LDW + c4 * 4;
        dstw[0] = f2tf32(v.x);
        dstw[1] = f2tf32(v.y);
        dstw[2] = f2tf32(v.z);
        dstw[3] = f2tf32(v.w);
    }
    for (int i = t; i < 128 * 32; i += 256) {  // W2: 128x128
        int r = i >> 5, c4 = i & 31;
        float4 v = ((const float4*)(w2 + (size_t)r * 128))[c4];
        uint32_t* dstw = W2s + r * LDW + c4 * 4;
        dstw[0] = f2tf32(v.x);
        dstw[1] = f2tf32(v.y);
        dstw[2] = f2tf32(v.z);
        dstw[3] = f2tf32(v.w);
    }
    if (t < 128) {
        b1s[t] = b1[t];
        b2s[t] = b2[t];
    }

    const int ntiles = N_EDGES / 128;  // 12500
    for (int tile = blockIdx.x; tile < ntiles; tile += gridDim.x) {
        const int e0 = tile * 128;
        __syncthreads();  // protect smem vs. previous iteration readers

        // Load edge_attr tile [128][64] -> tf32 smem
        for (int i = t; i < 128 * 16; i += 256) {
            int r = i >> 4, c4 = i & 15;
            float4 v =
                ((const float4*)(edge_attr + (size_t)(e0 + r) * 64))[c4];
            uint32_t* dstw = EAs + r * LDA_EA + c4 * 4;
            dstw[0] = f2tf32(v.x);
            dstw[1] = f2tf32(v.y);
            dstw[2] = f2tf32(v.z);
            dstw[3] = f2tf32(v.w);
        }
        if (t < 128) {
            int e = e0 + t;
            ss[t] = srcp[e];
            ds[t] = dstp[e];
            float l = elen[e];
            float c = 0.5f * (cosf(l * 0.31415926535897932f) + 1.0f);
            if (!(l <= 10.0f && l >= 0.0f)) c = 0.0f;
            Cs[t] = c;
        }
        __syncthreads();

        float acc[2][8][4];

        // ---- Stage 1: ts = ssp(EA @ W1 + b1), K = 64 ----
#pragma unroll
        for (int mi = 0; mi < 2; mi++)
#pragma unroll
            for (int ni = 0; ni < 8; ni++) {
                int col = n0c + ni * 8 + 2 * tid4;
                acc[mi][ni][0] = b1s[col];
                acc[mi][ni][1] = b1s[col + 1];
                acc[mi][ni][2] = b1s[col];
                acc[mi][ni][3] = b1s[col + 1];
            }
#pragma unroll
        for (int k0 = 0; k0 < 64; k0 += 8) {
            uint32_t afr[2][4];
#pragma unroll
            for (int mi = 0; mi < 2; mi++) {
                int ra = r0 + mi * 16 + gid;
                afr[mi][0] = EAs[ra * LDA_EA + k0 + tid4];
                afr[mi][1] = EAs[(ra + 8) * LDA_EA + k0 + tid4];
                afr[mi][2] = EAs[ra * LDA_EA + k0 + tid4 + 4];
                afr[mi][3] = EAs[(ra + 8) * LDA_EA + k0 + tid4 + 4];
            }
#pragma unroll
            for (int ni = 0; ni < 8; ni++) {
                int nn = n0c + ni * 8 + gid;
                uint32_t bf0 = W1s[(k0 + tid4) * LDW + nn];
                uint32_t bf1 = W1s[(k0 + tid4 + 4) * LDW + nn];
                mma_tf32(acc[0][ni], afr[0], bf0, bf1);
                mma_tf32(acc[1][ni], afr[1], bf0, bf1);
            }
        }
        // ssp -> tf32 -> ts
#pragma unroll
        for (int mi = 0; mi < 2; mi++) {
            int ra = r0 + mi * 16 + gid;
#pragma unroll
            for (int ni = 0; ni < 8; ni++) {
                int col = n0c + ni * 8 + 2 * tid4;
                tss[ra * LDA_TS + col] = f2tf32(sspf(acc[mi][ni][0]));
                tss[ra * LDA_TS + col + 1] = f2tf32(sspf(acc[mi][ni][1]));
                tss[(ra + 8) * LDA_TS + col] = f2tf32(sspf(acc[mi][ni][2]));
                tss[(ra + 8) * LDA_TS + col + 1] =
                    f2tf32(sspf(acc[mi][ni][3]));
            }
        }
        __syncthreads();

        // ---- Stage 2: W = ts @ W2 + b2, K = 128 ----
#pragma unroll
        for (int mi = 0; mi < 2; mi++)
#pragma unroll
            for (int ni = 0; ni < 8; ni++) {
                int col = n0c + ni * 8 + 2 * tid4;
                acc[mi][ni][0] = b2s[col];
                acc[mi][ni][1] = b2s[col + 1];
                acc[mi][ni][2] = b2s[col];
                acc[mi][ni][3] = b2s[col + 1];
            }
#pragma unroll
        for (int k0 = 0; k0 < 128; k0 += 8) {
            uint32_t afr[2][4];
#pragma unroll
            for (int mi = 0; mi < 2; mi++) {
                int ra = r0 + mi * 16 + gid;
                afr[mi][0] = tss[ra * LDA_TS + k0 + tid4];
                afr[mi][1] = tss[(ra + 8) * LDA_TS + k0 + tid4];
                afr[mi][2] = tss[ra * LDA_TS + k0 + tid4 + 4];
                afr[mi][3] = tss[(ra + 8) * LDA_TS + k0 + tid4 + 4];
            }
#pragma unroll
            for (int ni = 0; ni < 8; ni++) {
                int nn = n0c + ni * 8 + gid;
                uint32_t bf0 = W2s[(k0 + tid4) * LDW + nn];
                uint32_t bf1 = W2s[(k0 + tid4 + 4) * LDW + nn];
                mma_tf32(acc[0][ni], afr[0], bf0, bf1);
                mma_tf32(acc[1][ni], afr[1], bf0, bf1);
            }
        }

        // ---- Epilogue: envelope * gather(h[src]) -> red.v2 agg[dst] ----
#pragma unroll
        for (int mi = 0; mi < 2; mi++) {
            int rA = r0 + mi * 16 + gid;
            int rB = rA + 8;
            float CA = Cs[rA], CB = Cs[rB];
            const float* hA = g_h + (size_t)ss[rA] * 128;
            const float* hB = g_h + (size_t)ss[rB] * 128;
            float* aA = g_agg + (size_t)ds[rA] * 128;
            float* aB = g_agg + (size_t)ds[rB] * 128;
#pragma unroll
            for (int ni = 0; ni < 8; ni++) {
                int col = n0c + ni * 8 + 2 * tid4;
                float2 h2A = *(const float2*)(hA + col);
                float2 h2B = *(const float2*)(hB + col);
                red2(aA + col, acc[mi][ni][0] * CA * h2A.x,
                     acc[mi][ni][1] * CA * h2A.y);
                red2(aB + col, acc[mi][ni][2] * CB * h2B.x,
                     acc[mi][ni][3] * CB * h2B.y);
            }
        }
    }
}

__global__ void zero_kernel(float4* p, int n4) {
    int i = blockIdx.x * blockDim.x + threadIdx.x;
    if (i < n4) p[i] = make_float4(0.f, 0.f, 0.f, 0.f);
}

extern "C" void kernel_launch(void* const* d_in, const int* in_sizes, int n_in,
                              void* d_out, int out_size) {
    const float* x = (const float*)d_in[0];
    const int* eidx = (const int*)d_in[1];
    const float* elen = (const float*)d_in[2];
    const float* eattr = (const float*)d_in[3];
    const float* lin1_w = (const float*)d_in[4];
    const float* nn_w1 = (const float*)d_in[5];
    const float* nn_b1 = (const float*)d_in[6];
    const float* nn_w2 = (const float*)d_in[7];
    const float* nn_b2 = (const float*)d_in[8];
    const float* lin2_w = (const float*)d_in[9];
    const float* lin2_b = (const float*)d_in[10];
    const float* lin_w = (const float*)d_in[11];
    const float* lin_b = (const float*)d_in[12];
    float* out = (float*)d_out;

    float *h_p, *agg_p, *tmp_p;
    cudaGetSymbolAddress((void**)&h_p, g_h);
    cudaGetSymbolAddress((void**)&agg_p, g_agg);
    cudaGetSymbolAddress((void**)&tmp_p, g_tmp);

    const size_t gemm_smem = (size_t)(2 * 128 * 128 + 128) * sizeof(float);
    const size_t edge_smem =
        (size_t)(128 * LDA_EA + 64 * LDW + 128 * LDW + 128 * LDA_TS) * 4 +
        (size_t)(3 * 128) * sizeof(float) + 2 * 128 * sizeof(int);

    cudaFuncSetAttribute(gemm128_kernel<0, 0>,
                         cudaFuncAttributeMaxDynamicSharedMemorySize,
                         (int)gemm_smem);
    cudaFuncSetAttribute(gemm128_kernel<1, 1>,
                         cudaFuncAttributeMaxDynamicSharedMemorySize,
                         (int)gemm_smem);
    cudaFuncSetAttribute(gemm128_kernel<0, 1>,
                         cudaFuncAttributeMaxDynamicSharedMemorySize,
                         (int)gemm_smem);
    cudaFuncSetAttribute(edge_fused_kernel,
                         cudaFuncAttributeMaxDynamicSharedMemorySize,
                         (int)edge_smem);

    const int gridN = (N_NODES + 127) / 128;  // 391

    // 1) h = x @ lin1_w
    gemm128_kernel<0, 0><<<gridN, 256, gemm_smem>>>(x, lin1_w, nullptr, h_p,
                                                    N_NODES);
    // 2) agg = 0
    {
        int n4 = N_NODES * NFEAT / 4;
        zero_kernel<<<(n4 + 255) / 256, 256>>>((float4*)agg_p, n4);
    }
    // 3) fused edge MLP (tf32 tensor cores) + envelope + gather/scatter
    edge_fused_kernel<<<148, 256, edge_smem>>>(eattr, eidx, elen, nn_w1, nn_b1,
                                               nn_w2, nn_b2);
    // 4) tmp = ssp(agg @ lin2_w + lin2_b)
    gemm128_kernel<1, 1><<<gridN, 256, gemm_smem>>>(agg_p, lin2_w, lin2_b,
                                                    tmp_p, N_NODES);
    // 5) out = tmp @ lin_w + lin_b
    gemm128_kernel<0, 1><<<gridN, 256, gemm_smem>>>(tmp_p, lin_w, lin_b, out,
                                                    N_NODES);
}

// round 7
// speedup vs baseline: 2.0622x; 1.1166x over previous
#include <cuda_runtime.h>
#include <math.h>
#include <stdint.h>

#define N_NODES 50000
#define N_EDGES 1600000
#define HIDDIM 128
#define NFEAT 128
#define NGAUSS 64

__device__ float g_h[(size_t)N_NODES * NFEAT];
__device__ float g_agg[(size_t)N_NODES * NFEAT];
__device__ float g_tmp[(size_t)N_NODES * HIDDIM];

__device__ __forceinline__ float sspf(float v) {
    return fmaxf(v, 0.0f) + log1pf(expf(-fabsf(v))) - 0.69314718055994531f;
}

__device__ __forceinline__ uint32_t f2tf32(float f) {
    uint32_t r;
    asm("cvt.rna.tf32.f32 %0, %1;" : "=r"(r) : "f"(f));
    return r;
}

__device__ __forceinline__ void mma_tf32(float d[4], const uint32_t a[4],
                                         uint32_t b0, uint32_t b1) {
    asm volatile(
        "mma.sync.aligned.m16n8k8.row.col.f32.tf32.tf32.f32 "
        "{%0,%1,%2,%3}, {%4,%5,%6,%7}, {%8,%9}, {%0,%1,%2,%3};"
        : "+f"(d[0]), "+f"(d[1]), "+f"(d[2]), "+f"(d[3])
        : "r"(a[0]), "r"(a[1]), "r"(a[2]), "r"(a[3]), "r"(b0), "r"(b1));
}

__device__ __forceinline__ void red4(float* p, float v0, float v1, float v2,
                                     float v3) {
    asm volatile("red.global.add.v4.f32 [%0], {%1, %2, %3, %4};" ::"l"(p),
                 "f"(v0), "f"(v1), "f"(v2), "f"(v3)
                 : "memory");
}

// ---------------------------------------------------------------------------
// Node GEMM (fp32 FFMA): out[M,128] = act(A[M,128] @ W[128,128] + bias)
// 512 threads, 8x4 per-thread tile, padded A smem (broadcast a-loads).
// ---------------------------------------------------------------------------
#define LDAS 132
template <int ACT, int BIAS>
__global__ __launch_bounds__(512) void gemm128_kernel(
    const float* __restrict__ A, const float* __restrict__ W,
    const float* __restrict__ bias, float* __restrict__ out, int M) {
    extern __shared__ float sm[];
    float* As = sm;                    // 128*132
    float* Ws = sm + 128 * LDAS;       // 128*128
    float* bs = Ws + 128 * 128;        // 128

    const int t = threadIdx.x;
    const int row0 = blockIdx.x * 128;

    {
        const float4* Wg = (const float4*)W;
        float4* Wsh = (float4*)Ws;
        for (int i = t; i < 128 * 128 / 4; i += 512) Wsh[i] = Wg[i];
        if (t < 128) bs[t] = BIAS ? bias[t] : 0.0f;
    }
    for (int i = t; i < 128 * 32; i += 512) {
        int r = i >> 5, c = i & 31;
        int rg = row0 + r;
        float4 v = make_float4(0.f, 0.f, 0.f, 0.f);
        if (rg < M) v = ((const float4*)(A + (size_t)rg * 128))[c];
        *(float4*)(As + r * LDAS + c * 4) = v;
    }
    __syncthreads();

    const int tx = t & 31, ty = t >> 5;
    const int r0 = ty * 8, c0 = tx * 4;

    float acc[8][4];
#pragma unroll
    for (int i = 0; i < 8; i++) {
        float4 b0 = *(const float4*)(bs + c0);
        acc[i][0] = b0.x;
        acc[i][1] = b0.y;
        acc[i][2] = b0.z;
        acc[i][3] = b0.w;
    }

#pragma unroll 4
    for (int k = 0; k < 128; k++) {
        float4 bq = *(const float4*)(Ws + k * 128 + c0);
#pragma unroll
        for (int i = 0; i < 8; i++) {
            float a = As[(r0 + i) * LDAS + k];  // warp-broadcast
            acc[i][0] = fmaf(a, bq.x, acc[i][0]);
            acc[i][1] = fmaf(a, bq.y, acc[i][1]);
            acc[i][2] = fmaf(a, bq.z, acc[i][2]);
            acc[i][3] = fmaf(a, bq.w, acc[i][3]);
        }
    }

#pragma unroll
    for (int i = 0; i < 8; i++) {
        int rg = row0 + r0 + i;
        if (rg >= M) continue;
        float v0 = acc[i][0], v1 = acc[i][1], v2 = acc[i][2], v3 = acc[i][3];
        if (ACT == 1) {
            v0 = sspf(v0);
            v1 = sspf(v1);
            v2 = sspf(v2);
            v3 = sspf(v3);
        }
        *(float4*)(out + (size_t)rg * 128 + c0) = make_float4(v0, v1, v2, v3);
    }
}

// ---------------------------------------------------------------------------
// Fused edge kernel, tf32 tensor cores, 512 threads (16 warps).
// Warp tile 32x32 (2 mtiles x 4 ntiles of m16n8k8).
// After stage 2, acc*C is staged into smem (tss) and the epilogue does fully
// coalesced gather(h[src]) + red.global.add.v4.f32 scatter per edge row.
// ---------------------------------------------------------------------------
#define LDA_EA 68
#define LDA_TS 132
#define LDW 136

__global__ __launch_bounds__(512, 1) void edge_fused_kernel(
    const float* __restrict__ edge_attr, const int* __restrict__ eidx,
    const float* __restrict__ elen, const float* __restrict__ w1,
    const float* __restrict__ b1, const float* __restrict__ w2,
    const float* __restrict__ b2) {
    extern __shared__ uint32_t smu[];
    uint32_t* EAs = smu;                        // 128*68
    uint32_t* W1s = EAs + 128 * LDA_EA;         // 64*136
    uint32_t* W2s = W1s + 64 * LDW;             // 128*136
    uint32_t* tss = W2s + 128 * LDW;            // 128*132 (stage1 out / result)
    float* b1s = (float*)(tss + 128 * LDA_TS);  // 128
    float* b2s = b1s + 128;                     // 128
    float* Cs = b2s + 128;                      // 128
    int* ss = (int*)(Cs + 128);                 // 128
    int* ds = ss + 128;                         // 128
    float* tssf = (float*)tss;

    const int t = threadIdx.x;
    const int lane = t & 31, warp = t >> 5;
    const int gid = lane >> 2, tid4 = lane & 3;
    const int rg = warp & 3, cg = warp >> 2;  // 4 x 4
    const int r0 = rg * 32, n0c = cg * 32;
    const int* srcp = eidx;
    const int* dstp = eidx + N_EDGES;

    // One-time weight staging (tf32)
    for (int i = t; i < 64 * 32; i += 512) {
        int r = i >> 5, c4 = i & 31;
        float4 v = ((const float4*)(w1 + (size_t)r * 128))[c4];
        uint32_t* dstw = W1s + r * LDW + c4 * 4;
        dstw[0] = f2tf32(v.x);
        dstw[1] = f2tf32(v.y);
        dstw[2] = f2tf32(v.z);
        dstw[3] = f2tf32(v.w);
    }
    for (int i = t; i < 128 * 32; i += 512) {
        int r = i >> 5, c4 = i & 31;
        float4 v = ((const float4*)(w2 + (size_t)r * 128))[c4];
        uint32_t* dstw = W2s + r * LDW + c4 * 4;
        dstw[0] = f2tf32(v.x);
        dstw[1] = f2tf32(v.y);
        dstw[2] = f2tf32(v.z);
        dstw[3] = f2tf32(v.w);
    }
    if (t < 128) {
        b1s[t] = b1[t];
        b2s[t] = b2[t];
    }

    const int ntiles = N_EDGES / 128;  // 12500
    for (int tile = blockIdx.x; tile < ntiles; tile += gridDim.x) {
        const int e0 = tile * 128;
        __syncthreads();  // prev epilogue readers of tss/ss/ds done

        for (int i = t; i < 128 * 16; i += 512) {
            int r = i >> 4, c4 = i & 15;
            float4 v = ((const float4*)(edge_attr + (size_t)(e0 + r) * 64))[c4];
            uint32_t* dstw = EAs + r * LDA_EA + c4 * 4;
            dstw[0] = f2tf32(v.x);
            dstw[1] = f2tf32(v.y);
            dstw[2] = f2tf32(v.z);
            dstw[3] = f2tf32(v.w);
        }
        if (t < 128) {
            int e = e0 + t;
            ss[t] = srcp[e];
            ds[t] = dstp[e];
            float l = elen[e];
            float c = 0.5f * (cosf(l * 0.31415926535897932f) + 1.0f);
            if (!(l <= 10.0f && l >= 0.0f)) c = 0.0f;
            Cs[t] = c;
        }
        __syncthreads();

        float acc[2][4][4];

        // ---- Stage 1: ts = ssp(EA @ W1 + b1), K=64 ----
#pragma unroll
        for (int mi = 0; mi < 2; mi++)
#pragma unroll
            for (int ni = 0; ni < 4; ni++) {
                int col = n0c + ni * 8 + 2 * tid4;
                acc[mi][ni][0] = b1s[col];
                acc[mi][ni][1] = b1s[col + 1];
                acc[mi][ni][2] = b1s[col];
                acc[mi][ni][3] = b1s[col + 1];
            }
#pragma unroll
        for (int k0 = 0; k0 < 64; k0 += 8) {
            uint32_t afr[2][4];
#pragma unroll
            for (int mi = 0; mi < 2; mi++) {
                int ra = r0 + mi * 16 + gid;
                afr[mi][0] = EAs[ra * LDA_EA + k0 + tid4];
                afr[mi][1] = EAs[(ra + 8) * LDA_EA + k0 + tid4];
                afr[mi][2] = EAs[ra * LDA_EA + k0 + tid4 + 4];
                afr[mi][3] = EAs[(ra + 8) * LDA_EA + k0 + tid4 + 4];
            }
#pragma unroll
            for (int ni = 0; ni < 4; ni++) {
                int nn = n0c + ni * 8 + gid;
                uint32_t bf0 = W1s[(k0 + tid4) * LDW + nn];
                uint32_t bf1 = W1s[(k0 + tid4 + 4) * LDW + nn];
                mma_tf32(acc[0][ni], afr[0], bf0, bf1);
                mma_tf32(acc[1][ni], afr[1], bf0, bf1);
            }
        }
#pragma unroll
        for (int mi = 0; mi < 2; mi++) {
            int ra = r0 + mi * 16 + gid;
#pragma unroll
            for (int ni = 0; ni < 4; ni++) {
                int col = n0c + ni * 8 + 2 * tid4;
                uint2 lo = make_uint2(f2tf32(sspf(acc[mi][ni][0])),
                                      f2tf32(sspf(acc[mi][ni][1])));
                uint2 hi = make_uint2(f2tf32(sspf(acc[mi][ni][2])),
                                      f2tf32(sspf(acc[mi][ni][3])));
                *(uint2*)(tss + ra * LDA_TS + col) = lo;
                *(uint2*)(tss + (ra + 8) * LDA_TS + col) = hi;
            }
        }
        __syncthreads();

        // ---- Stage 2: W = ts @ W2 + b2, K=128 ----
#pragma unroll
        for (int mi = 0; mi < 2; mi++)
#pragma unroll
            for (int ni = 0; ni < 4; ni++) {
                int col = n0c + ni * 8 + 2 * tid4;
                acc[mi][ni][0] = b2s[col];
                acc[mi][ni][1] = b2s[col + 1];
                acc[mi][ni][2] = b2s[col];
                acc[mi][ni][3] = b2s[col + 1];
            }
#pragma unroll
        for (int k0 = 0; k0 < 128; k0 += 8) {
            uint32_t afr[2][4];
#pragma unroll
            for (int mi = 0; mi < 2; mi++) {
                int ra = r0 + mi * 16 + gid;
                afr[mi][0] = tss[ra * LDA_TS + k0 + tid4];
                afr[mi][1] = tss[(ra + 8) * LDA_TS + k0 + tid4];
                afr[mi][2] = tss[ra * LDA_TS + k0 + tid4 + 4];
                afr[mi][3] = tss[(ra + 8) * LDA_TS + k0 + tid4 + 4];
            }
#pragma unroll
            for (int ni = 0; ni < 4; ni++) {
                int nn = n0c + ni * 8 + gid;
                uint32_t bf0 = W2s[(k0 + tid4) * LDW + nn];
                uint32_t bf1 = W2s[(k0 + tid4 + 4) * LDW + nn];
                mma_tf32(acc[0][ni], afr[0], bf0, bf1);
                mma_tf32(acc[1][ni], afr[1], bf0, bf1);
            }
        }
        __syncthreads();  // all stage-2 reads of tss complete

        // Stage results*C back into tss (as fp32)
#pragma unroll
        for (int mi = 0; mi < 2; mi++) {
            int rA = r0 + mi * 16 + gid;
            int rB = rA + 8;
            float CA = Cs[rA], CB = Cs[rB];
#pragma unroll
            for (int ni = 0; ni < 4; ni++) {
                int col = n0c + ni * 8 + 2 * tid4;
                *(float2*)(tssf + rA * LDA_TS + col) =
                    make_float2(acc[mi][ni][0] * CA, acc[mi][ni][1] * CA);
                *(float2*)(tssf + rB * LDA_TS + col) =
                    make_float2(acc[mi][ni][2] * CB, acc[mi][ni][3] * CB);
            }
        }
        __syncthreads();

        // ---- Coalesced epilogue: 8 lanes per edge row ----
#pragma unroll
        for (int it = 0; it < 8; it++) {
            int idx = it * 512 + t;
            int r = idx >> 5, c4 = idx & 31;
            float4 w4 = *(const float4*)(tssf + r * LDA_TS + c4 * 4);
            const float* hrow = g_h + (size_t)ss[r] * 128 + c4 * 4;
            float4 h4 = *(const float4*)hrow;
            float* arow = g_agg + (size_t)ds[r] * 128 + c4 * 4;
            red4(arow, w4.x * h4.x, w4.y * h4.y, w4.z * h4.z, w4.w * h4.w);
        }
    }
}

__global__ void zero_kernel(float4* p, int n4) {
    int i = blockIdx.x * blockDim.x + threadIdx.x;
    if (i < n4) p[i] = make_float4(0.f, 0.f, 0.f, 0.f);
}

extern "C" void kernel_launch(void* const* d_in, const int* in_sizes, int n_in,
                              void* d_out, int out_size) {
    const float* x = (const float*)d_in[0];
    const int* eidx = (const int*)d_in[1];
    const float* elen = (const float*)d_in[2];
    const float* eattr = (const float*)d_in[3];
    const float* lin1_w = (const float*)d_in[4];
    const float* nn_w1 = (const float*)d_in[5];
    const float* nn_b1 = (const float*)d_in[6];
    const float* nn_w2 = (const float*)d_in[7];
    const float* nn_b2 = (const float*)d_in[8];
    const float* lin2_w = (const float*)d_in[9];
    const float* lin2_b = (const float*)d_in[10];
    const float* lin_w = (const float*)d_in[11];
    const float* lin_b = (const float*)d_in[12];
    float* out = (float*)d_out;

    float *h_p, *agg_p, *tmp_p;
    cudaGetSymbolAddress((void**)&h_p, g_h);
    cudaGetSymbolAddress((void**)&agg_p, g_agg);
    cudaGetSymbolAddress((void**)&tmp_p, g_tmp);

    const size_t gemm_smem =
        (size_t)(128 * LDAS + 128 * 128 + 128) * sizeof(float);
    const size_t edge_smem =
        (size_t)(128 * LDA_EA + 64 * LDW + 128 * LDW + 128 * LDA_TS) * 4 +
        (size_t)(3 * 128) * sizeof(float) + 2 * 128 * sizeof(int);

    cudaFuncSetAttribute(gemm128_kernel<0, 0>,
                         cudaFuncAttributeMaxDynamicSharedMemorySize,
                         (int)gemm_smem);
    cudaFuncSetAttribute(gemm128_kernel<1, 1>,
                         cudaFuncAttributeMaxDynamicSharedMemorySize,
                         (int)gemm_smem);
    cudaFuncSetAttribute(gemm128_kernel<0, 1>,
                         cudaFuncAttributeMaxDynamicSharedMemorySize,
                         (int)gemm_smem);
    cudaFuncSetAttribute(edge_fused_kernel,
                         cudaFuncAttributeMaxDynamicSharedMemorySize,
                         (int)edge_smem);

    const int gridN = (N_NODES + 127) / 128;  // 391

    gemm128_kernel<0, 0><<<gridN, 512, gemm_smem>>>(x, lin1_w, nullptr, h_p,
                                                    N_NODES);
    {
        int n4 = N_NODES * NFEAT / 4;
        zero_kernel<<<(n4 + 255) / 256, 256>>>((float4*)agg_p, n4);
    }
    edge_fused_kernel<<<148, 512, edge_smem>>>(eattr, eidx, elen, nn_w1, nn_b1,
                                               nn_w2, nn_b2);
    gemm128_kernel<1, 1><<<gridN, 512, gemm_smem>>>(agg_p, lin2_w, lin2_b,
                                                    tmp_p, N_NODES);
    gemm128_kernel<0, 1><<<gridN, 512, gemm_smem>>>(tmp_p, lin_w, lin_b, out,
                                                    N_NODES);
}

// round 8
// speedup vs baseline: 2.3525x; 1.1408x over previous
#include <cuda_runtime.h>
#include <math.h>
#include <stdint.h>

#define N_NODES 50000
#define N_EDGES 1600000
#define HIDDIM 128
#define NFEAT 128
#define NGAUSS 64

__device__ float g_h[(size_t)N_NODES * NFEAT];
__device__ float g_agg[(size_t)N_NODES * NFEAT];
__device__ float g_tmp[(size_t)N_NODES * HIDDIM];

__device__ __forceinline__ float sspf(float v) {
    return fmaxf(v, 0.0f) + log1pf(expf(-fabsf(v))) - 0.69314718055994531f;
}

__device__ __forceinline__ uint32_t f2tf32(float f) {
    uint32_t r;
    asm("cvt.rna.tf32.f32 %0, %1;" : "=r"(r) : "f"(f));
    return r;
}

__device__ __forceinline__ void mma_tf32(float d[4], const uint32_t a[4],
                                         uint32_t b0, uint32_t b1) {
    asm volatile(
        "mma.sync.aligned.m16n8k8.row.col.f32.tf32.tf32.f32 "
        "{%0,%1,%2,%3}, {%4,%5,%6,%7}, {%8,%9}, {%0,%1,%2,%3};"
        : "+f"(d[0]), "+f"(d[1]), "+f"(d[2]), "+f"(d[3])
        : "r"(a[0]), "r"(a[1]), "r"(a[2]), "r"(a[3]), "r"(b0), "r"(b1));
}

__device__ __forceinline__ void red4(float* p, float v0, float v1, float v2,
                                     float v3) {
    asm volatile("red.global.add.v4.f32 [%0], {%1, %2, %3, %4};" ::"l"(p),
                 "f"(v0), "f"(v1), "f"(v2), "f"(v3)
                 : "memory");
}

__device__ __forceinline__ void gbar(int id) {
    asm volatile("bar.sync %0, 256;" ::"r"(id) : "memory");
}

// ---------------------------------------------------------------------------
// Node GEMM (fp32 FFMA): out[M,128] = act(A[M,128] @ W[128,128] + bias)
// ---------------------------------------------------------------------------
#define LDAS 132
template <int ACT, int BIAS>
__global__ __launch_bounds__(512) void gemm128_kernel(
    const float* __restrict__ A, const float* __restrict__ W,
    const float* __restrict__ bias, float* __restrict__ out, int M) {
    extern __shared__ float sm[];
    float* As = sm;
    float* Ws = sm + 128 * LDAS;
    float* bs = Ws + 128 * 128;

    const int t = threadIdx.x;
    const int row0 = blockIdx.x * 128;

    {
        const float4* Wg = (const float4*)W;
        float4* Wsh = (float4*)Ws;
        for (int i = t; i < 128 * 128 / 4; i += 512) Wsh[i] = Wg[i];
        if (t < 128) bs[t] = BIAS ? bias[t] : 0.0f;
    }
    for (int i = t; i < 128 * 32; i += 512) {
        int r = i >> 5, c = i & 31;
        int rg = row0 + r;
        float4 v = make_float4(0.f, 0.f, 0.f, 0.f);
        if (rg < M) v = ((const float4*)(A + (size_t)rg * 128))[c];
        *(float4*)(As + r * LDAS + c * 4) = v;
    }
    __syncthreads();

    const int tx = t & 31, ty = t >> 5;
    const int r0 = ty * 8, c0 = tx * 4;

    float acc[8][4];
#pragma unroll
    for (int i = 0; i < 8; i++) {
        float4 b0 = *(const float4*)(bs + c0);
        acc[i][0] = b0.x;
        acc[i][1] = b0.y;
        acc[i][2] = b0.z;
        acc[i][3] = b0.w;
    }

#pragma unroll 4
    for (int k = 0; k < 128; k++) {
        float4 bq = *(const float4*)(Ws + k * 128 + c0);
#pragma unroll
        for (int i = 0; i < 8; i++) {
            float a = As[(r0 + i) * LDAS + k];
            acc[i][0] = fmaf(a, bq.x, acc[i][0]);
            acc[i][1] = fmaf(a, bq.y, acc[i][1]);
            acc[i][2] = fmaf(a, bq.z, acc[i][2]);
            acc[i][3] = fmaf(a, bq.w, acc[i][3]);
        }
    }

#pragma unroll
    for (int i = 0; i < 8; i++) {
        int rg = row0 + r0 + i;
        if (rg >= M) continue;
        float v0 = acc[i][0], v1 = acc[i][1], v2 = acc[i][2], v3 = acc[i][3];
        if (ACT == 1) {
            v0 = sspf(v0);
            v1 = sspf(v1);
            v2 = sspf(v2);
            v3 = sspf(v3);
        }
        *(float4*)(out + (size_t)rg * 128 + c0) = make_float4(v0, v1, v2, v3);
    }
}

// ---------------------------------------------------------------------------
// Fused edge kernel: tf32 MMA, 512 threads = 2 independent groups of 8 warps.
// Each group runs its own stream of 64-edge x 128-feat tiles with private
// smem buffers; groups share only the read-only weight smem and sync among
// themselves with named barriers. Group phase skew overlaps one group's
// L2 gather/scatter epilogue with the other group's tensor-core phases.
// ---------------------------------------------------------------------------
#define LDA_EA 68
#define LDA_TS 132
#define LDW 136
#define TEDGE 64

__global__ __launch_bounds__(512, 1) void edge_fused_kernel(
    const float* __restrict__ edge_attr, const int* __restrict__ eidx,
    const float* __restrict__ elen, const float* __restrict__ w1,
    const float* __restrict__ b1, const float* __restrict__ w2,
    const float* __restrict__ b2) {
    extern __shared__ uint32_t smu[];
    uint32_t* W1s = smu;                         // 64*136   = 8704
    uint32_t* W2s = W1s + 64 * LDW;              // 128*136  = 17408
    uint32_t* EAsA = W2s + 128 * LDW;            // 2*64*68  = 8704
    uint32_t* tssA = EAsA + 2 * TEDGE * LDA_EA;  // 2*64*132 = 16896
    float* b1s = (float*)(tssA + 2 * TEDGE * LDA_TS);  // 128
    float* b2s = b1s + 128;                            // 128
    float* CsA = b2s + 128;                            // 2*64
    int* ssA = (int*)(CsA + 2 * TEDGE);                // 2*64
    int* dsA = ssA + 2 * TEDGE;                        // 2*64

    const int t = threadIdx.x;
    const int lane = t & 31, warp = t >> 5;
    const int g = warp >> 3;        // group 0/1
    const int w8 = warp & 7;        // warp within group
    const int tg = t & 255;         // thread within group
    const int gid = lane >> 2, tid4 = lane & 3;
    const int rg = w8 & 1, cg = w8 >> 1;  // 2 row-groups x 4 col-groups
    const int r0 = rg * 32, n0c = cg * 32;
    const int* srcp = eidx;
    const int* dstp = eidx + N_EDGES;

    uint32_t* EAs = EAsA + g * TEDGE * LDA_EA;
    uint32_t* tss = tssA + g * TEDGE * LDA_TS;
    float* tssf = (float*)tss;
    float* Cs = CsA + g * TEDGE;
    int* ss = ssA + g * TEDGE;
    int* ds = dsA + g * TEDGE;
    const int bid = 1 + g;  // named barrier id

    // One-time weight staging (all 512 threads cooperate)
    for (int i = t; i < 64 * 32; i += 512) {
        int r = i >> 5, c4 = i & 31;
        float4 v = ((const float4*)(w1 + (size_t)r * 128))[c4];
        uint32_t* dstw = W1s + r * LDW + c4 * 4;
        dstw[0] = f2tf32(v.x);
        dstw[1] = f2tf32(v.y);
        dstw[2] = f2tf32(v.z);
        dstw[3] = f2tf32(v.w);
    }
    for (int i = t; i < 128 * 32; i += 512) {
        int r = i >> 5, c4 = i & 31;
        float4 v = ((const float4*)(w2 + (size_t)r * 128))[c4];
        uint32_t* dstw = W2s + r * LDW + c4 * 4;
        dstw[0] = f2tf32(v.x);
        dstw[1] = f2tf32(v.y);
        dstw[2] = f2tf32(v.z);
        dstw[3] = f2tf32(v.w);
    }
    if (t < 128) {
        b1s[t] = b1[t];
        b2s[t] = b2[t];
    }
    __syncthreads();

    const int ntiles = N_EDGES / TEDGE;  // 25000
    const int stride = 2 * gridDim.x;
    for (int tile = blockIdx.x * 2 + g; tile < ntiles; tile += stride) {
        const int e0 = tile * TEDGE;
        gbar(bid);  // previous-iteration readers of this group's smem done

        // Load edge_attr tile [64][64] -> tf32 smem
        for (int i = tg; i < TEDGE * 16; i += 256) {
            int r = i >> 4, c4 = i & 15;
            float4 v = ((const float4*)(edge_attr + (size_t)(e0 + r) * 64))[c4];
            uint32_t* dstw = EAs + r * LDA_EA + c4 * 4;
            dstw[0] = f2tf32(v.x);
            dstw[1] = f2tf32(v.y);
            dstw[2] = f2tf32(v.z);
            dstw[3] = f2tf32(v.w);
        }
        if (tg < TEDGE) {
            int e = e0 + tg;
            ss[tg] = srcp[e];
            ds[tg] = dstp[e];
            float l = elen[e];
            float c = 0.5f * (cosf(l * 0.31415926535897932f) + 1.0f);
            if (!(l <= 10.0f && l >= 0.0f)) c = 0.0f;
            Cs[tg] = c;
        }
        gbar(bid);

        float acc[2][4][4];

        // ---- Stage 1: ts = ssp(EA @ W1 + b1), K=64 ----
#pragma unroll
        for (int mi = 0; mi < 2; mi++)
#pragma unroll
            for (int ni = 0; ni < 4; ni++) {
                int col = n0c + ni * 8 + 2 * tid4;
                acc[mi][ni][0] = b1s[col];
                acc[mi][ni][1] = b1s[col + 1];
                acc[mi][ni][2] = b1s[col];
                acc[mi][ni][3] = b1s[col + 1];
            }
#pragma unroll
        for (int k0 = 0; k0 < 64; k0 += 8) {
            uint32_t afr[2][4];
#pragma unroll
            for (int mi = 0; mi < 2; mi++) {
                int ra = r0 + mi * 16 + gid;
                afr[mi][0] = EAs[ra * LDA_EA + k0 + tid4];
                afr[mi][1] = EAs[(ra + 8) * LDA_EA + k0 + tid4];
                afr[mi][2] = EAs[ra * LDA_EA + k0 + tid4 + 4];
                afr[mi][3] = EAs[(ra + 8) * LDA_EA + k0 + tid4 + 4];
            }
#pragma unroll
            for (int ni = 0; ni < 4; ni++) {
                int nn = n0c + ni * 8 + gid;
                uint32_t bf0 = W1s[(k0 + tid4) * LDW + nn];
                uint32_t bf1 = W1s[(k0 + tid4 + 4) * LDW + nn];
                mma_tf32(acc[0][ni], afr[0], bf0, bf1);
                mma_tf32(acc[1][ni], afr[1], bf0, bf1);
            }
        }
#pragma unroll
        for (int mi = 0; mi < 2; mi++) {
            int ra = r0 + mi * 16 + gid;
#pragma unroll
            for (int ni = 0; ni < 4; ni++) {
                int col = n0c + ni * 8 + 2 * tid4;
                uint2 lo = make_uint2(f2tf32(sspf(acc[mi][ni][0])),
                                      f2tf32(sspf(acc[mi][ni][1])));
                uint2 hi = make_uint2(f2tf32(sspf(acc[mi][ni][2])),
                                      f2tf32(sspf(acc[mi][ni][3])));
                *(uint2*)(tss + ra * LDA_TS + col) = lo;
                *(uint2*)(tss + (ra + 8) * LDA_TS + col) = hi;
            }
        }
        gbar(bid);

        // ---- Stage 2: W = ts @ W2 + b2, K=128 ----
#pragma unroll
        for (int mi = 0; mi < 2; mi++)
#pragma unroll
            for (int ni = 0; ni < 4; ni++) {
                int col = n0c + ni * 8 + 2 * tid4;
                acc[mi][ni][0] = b2s[col];
                acc[mi][ni][1] = b2s[col + 1];
                acc[mi][ni][2] = b2s[col];
                acc[mi][ni][3] = b2s[col + 1];
            }
#pragma unroll
        for (int k0 = 0; k0 < 128; k0 += 8) {
            uint32_t afr[2][4];
#pragma unroll
            for (int mi = 0; mi < 2; mi++) {
                int ra = r0 + mi * 16 + gid;
                afr[mi][0] = tss[ra * LDA_TS + k0 + tid4];
                afr[mi][1] = tss[(ra + 8) * LDA_TS + k0 + tid4];
                afr[mi][2] = tss[ra * LDA_TS + k0 + tid4 + 4];
                afr[mi][3] = tss[(ra + 8) * LDA_TS + k0 + tid4 + 4];
            }
#pragma unroll
            for (int ni = 0; ni < 4; ni++) {
                int nn = n0c + ni * 8 + gid;
                uint32_t bf0 = W2s[(k0 + tid4) * LDW + nn];
                uint32_t bf1 = W2s[(k0 + tid4 + 4) * LDW + nn];
                mma_tf32(acc[0][ni], afr[0], bf0, bf1);
                mma_tf32(acc[1][ni], afr[1], bf0, bf1);
            }
        }
        gbar(bid);  // stage-2 reads of tss complete

        // Stage results*C back into tss (fp32)
#pragma unroll
        for (int mi = 0; mi < 2; mi++) {
            int rA = r0 + mi * 16 + gid;
            int rB = rA + 8;
            float CA = Cs[rA], CB = Cs[rB];
#pragma unroll
            for (int ni = 0; ni < 4; ni++) {
                int col = n0c + ni * 8 + 2 * tid4;
                *(float2*)(tssf + rA * LDA_TS + col) =
                    make_float2(acc[mi][ni][0] * CA, acc[mi][ni][1] * CA);
                *(float2*)(tssf + rB * LDA_TS + col) =
                    make_float2(acc[mi][ni][2] * CB, acc[mi][ni][3] * CB);
            }
        }
        gbar(bid);

        // ---- Coalesced epilogue: 8 lanes per edge row ----
#pragma unroll
        for (int it = 0; it < 8; it++) {
            int idx = it * 256 + tg;
            int r = idx >> 5, c4 = idx & 31;
            float4 w4 = *(const float4*)(tssf + r * LDA_TS + c4 * 4);
            const float* hrow = g_h + (size_t)ss[r] * 128 + c4 * 4;
            float4 h4 = *(const float4*)hrow;
            float* arow = g_agg + (size_t)ds[r] * 128 + c4 * 4;
            red4(arow, w4.x * h4.x, w4.y * h4.y, w4.z * h4.z, w4.w * h4.w);
        }
    }
}

__global__ void zero_kernel(float4* p, int n4) {
    int i = blockIdx.x * blockDim.x + threadIdx.x;
    if (i < n4) p[i] = make_float4(0.f, 0.f, 0.f, 0.f);
}

extern "C" void kernel_launch(void* const* d_in, const int* in_sizes, int n_in,
                              void* d_out, int out_size) {
    const float* x = (const float*)d_in[0];
    const int* eidx = (const int*)d_in[1];
    const float* elen = (const float*)d_in[2];
    const float* eattr = (const float*)d_in[3];
    const float* lin1_w = (const float*)d_in[4];
    const float* nn_w1 = (const float*)d_in[5];
    const float* nn_b1 = (const float*)d_in[6];
    const float* nn_w2 = (const float*)d_in[7];
    const float* nn_b2 = (const float*)d_in[8];
    const float* lin2_w = (const float*)d_in[9];
    const float* lin2_b = (const float*)d_in[10];
    const float* lin_w = (const float*)d_in[11];
    const float* lin_b = (const float*)d_in[12];
    float* out = (float*)d_out;

    float *h_p, *agg_p, *tmp_p;
    cudaGetSymbolAddress((void**)&h_p, g_h);
    cudaGetSymbolAddress((void**)&agg_p, g_agg);
    cudaGetSymbolAddress((void**)&tmp_p, g_tmp);

    const size_t gemm_smem =
        (size_t)(128 * LDAS + 128 * 128 + 128) * sizeof(float);
    const size_t edge_smem =
        (size_t)(64 * LDW + 128 * LDW + 2 * TEDGE * LDA_EA +
                 2 * TEDGE * LDA_TS) *
            4 +
        (size_t)(2 * 128 + 2 * TEDGE) * sizeof(float) +
        (size_t)(4 * TEDGE) * sizeof(int);

    cudaFuncSetAttribute(gemm128_kernel<0, 0>,
                         cudaFuncAttributeMaxDynamicSharedMemorySize,
                         (int)gemm_smem);
    cudaFuncSetAttribute(gemm128_kernel<1, 1>,
                         cudaFuncAttributeMaxDynamicSharedMemorySize,
                         (int)gemm_smem);
    cudaFuncSetAttribute(gemm128_kernel<0, 1>,
                         cudaFuncAttributeMaxDynamicSharedMemorySize,
                         (int)gemm_smem);
    cudaFuncSetAttribute(edge_fused_kernel,
                         cudaFuncAttributeMaxDynamicSharedMemorySize,
                         (int)edge_smem);

    const int gridN = (N_NODES + 127) / 128;  // 391

    gemm128_kernel<0, 0><<<gridN, 512, gemm_smem>>>(x, lin1_w, nullptr, h_p,
                                                    N_NODES);
    {
        int n4 = N_NODES * NFEAT / 4;
        zero_kernel<<<(n4 + 255) / 256, 256>>>((float4*)agg_p, n4);
    }
    edge_fused_kernel<<<148, 512, edge_smem>>>(eattr, eidx, elen, nn_w1, nn_b1,
                                               nn_w2, nn_b2);
    gemm128_kernel<1, 1><<<gridN, 512, gemm_smem>>>(agg_p, lin2_w, lin2_b,
                                                    tmp_p, N_NODES);
    gemm128_kernel<0, 1><<<gridN, 512, gemm_smem>>>(tmp_p, lin_w, lin_b, out,
                                                    N_NODES);
}

// round 9
// speedup vs baseline: 2.8633x; 1.2171x over previous
#include <cuda_runtime.h>
#include <math.h>
#include <stdint.h>

#define N_NODES 50000
#define N_EDGES 1600000
#define HIDDIM 128
#define NFEAT 128
#define NGAUSS 64

__device__ float g_h[(size_t)N_NODES * NFEAT];
__device__ float g_agg[(size_t)N_NODES * NFEAT];
__device__ float g_tmp[(size_t)N_NODES * HIDDIM];

__device__ __forceinline__ float sspf(float v) {
    return fmaxf(v, 0.0f) + log1pf(expf(-fabsf(v))) - 0.69314718055994531f;
}

__device__ __forceinline__ uint32_t f2tf32(float f) {
    uint32_t r;
    asm("cvt.rna.tf32.f32 %0, %1;" : "=r"(r) : "f"(f));
    return r;
}

__device__ __forceinline__ void mma_tf32(float d[4], const uint32_t a[4],
                                         uint32_t b0, uint32_t b1) {
    asm volatile(
        "mma.sync.aligned.m16n8k8.row.col.f32.tf32.tf32.f32 "
        "{%0,%1,%2,%3}, {%4,%5,%6,%7}, {%8,%9}, {%0,%1,%2,%3};"
        : "+f"(d[0]), "+f"(d[1]), "+f"(d[2]), "+f"(d[3])
        : "r"(a[0]), "r"(a[1]), "r"(a[2]), "r"(a[3]), "r"(b0), "r"(b1));
}

__device__ __forceinline__ void red4(float* p, float v0, float v1, float v2,
                                     float v3) {
    asm volatile("red.global.add.v4.f32 [%0], {%1, %2, %3, %4};" ::"l"(p),
                 "f"(v0), "f"(v1), "f"(v2), "f"(v3)
                 : "memory");
}

__device__ __forceinline__ void gbar(int id) {
    asm volatile("bar.sync %0, 128;" ::"r"(id) : "memory");
}

#define LDA_EA 68
#define LDA_TS 132
#define LDW 136
#define TEDGE 32

// ---------------------------------------------------------------------------
// Node GEMM, tf32 tensor cores: out[M,128] = act(A[M,128] @ W[128,128] + b)
// 512 threads = 16 warps; tile 128 rows; warp tile 32x32 (2m x 4n m16n8k8).
// ---------------------------------------------------------------------------
template <int ACT, int BIAS>
__global__ __launch_bounds__(512) void gemm128_tf32_kernel(
    const float* __restrict__ A, const float* __restrict__ W,
    const float* __restrict__ bias, float* __restrict__ out, int M) {
    extern __shared__ uint32_t smu[];
    uint32_t* As = smu;                 // 128*132
    uint32_t* Ws = As + 128 * LDA_TS;   // 128*136
    float* bs = (float*)(Ws + 128 * LDW);  // 128

    const int t = threadIdx.x;
    const int row0 = blockIdx.x * 128;
    const int lane = t & 31, warp = t >> 5;
    const int gid = lane >> 2, tid4 = lane & 3;
    const int wr = warp & 3, cg = warp >> 2;
    const int r0 = wr * 32, n0c = cg * 32;

    for (int i = t; i < 128 * 32; i += 512) {
        int r = i >> 5, c4 = i & 31;
        float4 v = ((const float4*)(W + (size_t)r * 128))[c4];
        uint32_t* dst = Ws + r * LDW + c4 * 4;
        dst[0] = f2tf32(v.x);
        dst[1] = f2tf32(v.y);
        dst[2] = f2tf32(v.z);
        dst[3] = f2tf32(v.w);
    }
    for (int i = t; i < 128 * 32; i += 512) {
        int r = i >> 5, c4 = i & 31;
        int rg = row0 + r;
        float4 v = make_float4(0.f, 0.f, 0.f, 0.f);
        if (rg < M) v = ((const float4*)(A + (size_t)rg * 128))[c4];
        uint32_t* dst = As + r * LDA_TS + c4 * 4;
        dst[0] = f2tf32(v.x);
        dst[1] = f2tf32(v.y);
        dst[2] = f2tf32(v.z);
        dst[3] = f2tf32(v.w);
    }
    if (t < 128) bs[t] = BIAS ? bias[t] : 0.0f;
    __syncthreads();

    float acc[2][4][4];
#pragma unroll
    for (int mi = 0; mi < 2; mi++)
#pragma unroll
        for (int ni = 0; ni < 4; ni++) {
            int col = n0c + ni * 8 + 2 * tid4;
            acc[mi][ni][0] = bs[col];
            acc[mi][ni][1] = bs[col + 1];
            acc[mi][ni][2] = bs[col];
            acc[mi][ni][3] = bs[col + 1];
        }
#pragma unroll
    for (int k0 = 0; k0 < 128; k0 += 8) {
        uint32_t afr[2][4];
#pragma unroll
        for (int mi = 0; mi < 2; mi++) {
            int ra = r0 + mi * 16 + gid;
            afr[mi][0] = As[ra * LDA_TS + k0 + tid4];
            afr[mi][1] = As[(ra + 8) * LDA_TS + k0 + tid4];
            afr[mi][2] = As[ra * LDA_TS + k0 + tid4 + 4];
            afr[mi][3] = As[(ra + 8) * LDA_TS + k0 + tid4 + 4];
        }
#pragma unroll
        for (int ni = 0; ni < 4; ni++) {
            int nn = n0c + ni * 8 + gid;
            uint32_t bf0 = Ws[(k0 + tid4) * LDW + nn];
            uint32_t bf1 = Ws[(k0 + tid4 + 4) * LDW + nn];
            mma_tf32(acc[0][ni], afr[0], bf0, bf1);
            mma_tf32(acc[1][ni], afr[1], bf0, bf1);
        }
    }

#pragma unroll
    for (int mi = 0; mi < 2; mi++) {
#pragma unroll
        for (int half = 0; half < 2; half++) {
            int rg = row0 + r0 + mi * 16 + gid + half * 8;
            if (rg >= M) continue;
            float* orow = out + (size_t)rg * 128;
#pragma unroll
            for (int ni = 0; ni < 4; ni++) {
                int col = n0c + ni * 8 + 2 * tid4;
                float v0 = acc[mi][ni][half * 2 + 0];
                float v1 = acc[mi][ni][half * 2 + 1];
                if (ACT == 1) {
                    v0 = sspf(v0);
                    v1 = sspf(v1);
                }
                *(float2*)(orow + col) = make_float2(v0, v1);
            }
        }
    }
}

// ---------------------------------------------------------------------------
// Fused edge kernel: tf32 MMA, 512 threads = 4 independent groups of 4 warps
// (one warp per SMSP per group). Each group streams 32-edge x 128-feat tiles
// with private smem; groups sync only via their own named barrier, so the 4
// phase streams interleave MMA / LDS / gather / scatter per scheduler.
// ---------------------------------------------------------------------------
__global__ __launch_bounds__(512, 1) void edge_fused_kernel(
    const float* __restrict__ edge_attr, const int* __restrict__ eidx,
    const float* __restrict__ elen, const float* __restrict__ w1,
    const float* __restrict__ b1, const float* __restrict__ w2,
    const float* __restrict__ b2) {
    extern __shared__ uint32_t smu[];
    uint32_t* W1s = smu;                         // 64*136
    uint32_t* W2s = W1s + 64 * LDW;              // 128*136
    uint32_t* EAsA = W2s + 128 * LDW;            // 4*32*68
    uint32_t* tssA = EAsA + 4 * TEDGE * LDA_EA;  // 4*32*132
    float* b1s = (float*)(tssA + 4 * TEDGE * LDA_TS);  // 128
    float* b2s = b1s + 128;                            // 128
    float* CsA = b2s + 128;                            // 4*32
    int* ssA = (int*)(CsA + 4 * TEDGE);                // 4*32
    int* dsA = ssA + 4 * TEDGE;                        // 4*32

    const int t = threadIdx.x;
    const int lane = t & 31, warp = t >> 5;
    const int g = warp >> 2;   // group 0..3
    const int w4 = warp & 3;   // warp within group
    const int tg = t & 127;    // thread within group
    const int gid = lane >> 2, tid4 = lane & 3;
    const int n0c = w4 * 32;
    const int* srcp = eidx;
    const int* dstp = eidx + N_EDGES;

    uint32_t* EAs = EAsA + g * TEDGE * LDA_EA;
    uint32_t* tss = tssA + g * TEDGE * LDA_TS;
    float* tssf = (float*)tss;
    float* Cs = CsA + g * TEDGE;
    int* ss = ssA + g * TEDGE;
    int* ds = dsA + g * TEDGE;
    const int bid = 1 + g;

    // One-time weight staging (all 512 threads)
    for (int i = t; i < 64 * 32; i += 512) {
        int r = i >> 5, c4 = i & 31;
        float4 v = ((const float4*)(w1 + (size_t)r * 128))[c4];
        uint32_t* dstw = W1s + r * LDW + c4 * 4;
        dstw[0] = f2tf32(v.x);
        dstw[1] = f2tf32(v.y);
        dstw[2] = f2tf32(v.z);
        dstw[3] = f2tf32(v.w);
    }
    for (int i = t; i < 128 * 32; i += 512) {
        int r = i >> 5, c4 = i & 31;
        float4 v = ((const float4*)(w2 + (size_t)r * 128))[c4];
        uint32_t* dstw = W2s + r * LDW + c4 * 4;
        dstw[0] = f2tf32(v.x);
        dstw[1] = f2tf32(v.y);
        dstw[2] = f2tf32(v.z);
        dstw[3] = f2tf32(v.w);
    }
    if (t < 128) {
        b1s[t] = b1[t];
        b2s[t] = b2[t];
    }
    __syncthreads();

    const int ntiles = N_EDGES / TEDGE;  // 50000
    const int stride = 4 * gridDim.x;
    for (int tile = blockIdx.x * 4 + g; tile < ntiles; tile += stride) {
        const int e0 = tile * TEDGE;
        gbar(bid);  // prior epilogue readers of this group's smem done

        // Load edge_attr tile [32][64] -> tf32 smem
        for (int i = tg; i < TEDGE * 16; i += 128) {
            int r = i >> 4, c4 = i & 15;
            float4 v = ((const float4*)(edge_attr + (size_t)(e0 + r) * 64))[c4];
            uint32_t* dstw = EAs + r * LDA_EA + c4 * 4;
            dstw[0] = f2tf32(v.x);
            dstw[1] = f2tf32(v.y);
            dstw[2] = f2tf32(v.z);
            dstw[3] = f2tf32(v.w);
        }
        if (tg < TEDGE) {
            int e = e0 + tg;
            ss[tg] = srcp[e];
            ds[tg] = dstp[e];
            float l = elen[e];
            float c = 0.5f * (cosf(l * 0.31415926535897932f) + 1.0f);
            if (!(l <= 10.0f && l >= 0.0f)) c = 0.0f;
            Cs[tg] = c;
        }
        gbar(bid);

        float acc[2][4][4];

        // ---- Stage 1: ts = ssp(EA @ W1 + b1), K=64 ----
#pragma unroll
        for (int mi = 0; mi < 2; mi++)
#pragma unroll
            for (int ni = 0; ni < 4; ni++) {
                int col = n0c + ni * 8 + 2 * tid4;
                acc[mi][ni][0] = b1s[col];
                acc[mi][ni][1] = b1s[col + 1];
                acc[mi][ni][2] = b1s[col];
                acc[mi][ni][3] = b1s[col + 1];
            }
#pragma unroll
        for (int k0 = 0; k0 < 64; k0 += 8) {
            uint32_t afr[2][4];
#pragma unroll
            for (int mi = 0; mi < 2; mi++) {
                int ra = mi * 16 + gid;
                afr[mi][0] = EAs[ra * LDA_EA + k0 + tid4];
                afr[mi][1] = EAs[(ra + 8) * LDA_EA + k0 + tid4];
                afr[mi][2] = EAs[ra * LDA_EA + k0 + tid4 + 4];
                afr[mi][3] = EAs[(ra + 8) * LDA_EA + k0 + tid4 + 4];
            }
#pragma unroll
            for (int ni = 0; ni < 4; ni++) {
                int nn = n0c + ni * 8 + gid;
                uint32_t bf0 = W1s[(k0 + tid4) * LDW + nn];
                uint32_t bf1 = W1s[(k0 + tid4 + 4) * LDW + nn];
                mma_tf32(acc[0][ni], afr[0], bf0, bf1);
                mma_tf32(acc[1][ni], afr[1], bf0, bf1);
            }
        }
#pragma unroll
        for (int mi = 0; mi < 2; mi++) {
            int ra = mi * 16 + gid;
#pragma unroll
            for (int ni = 0; ni < 4; ni++) {
                int col = n0c + ni * 8 + 2 * tid4;
                uint2 lo = make_uint2(f2tf32(sspf(acc[mi][ni][0])),
                                      f2tf32(sspf(acc[mi][ni][1])));
                uint2 hi = make_uint2(f2tf32(sspf(acc[mi][ni][2])),
                                      f2tf32(sspf(acc[mi][ni][3])));
                *(uint2*)(tss + ra * LDA_TS + col) = lo;
                *(uint2*)(tss + (ra + 8) * LDA_TS + col) = hi;
            }
        }
        gbar(bid);

        // ---- Stage 2: W = ts @ W2 + b2, K=128 ----
#pragma unroll
        for (int mi = 0; mi < 2; mi++)
#pragma unroll
            for (int ni = 0; ni < 4; ni++) {
                int col = n0c + ni * 8 + 2 * tid4;
                acc[mi][ni][0] = b2s[col];
                acc[mi][ni][1] = b2s[col + 1];
                acc[mi][ni][2] = b2s[col];
                acc[mi][ni][3] = b2s[col + 1];
            }
#pragma unroll
        for (int k0 = 0; k0 < 128; k0 += 8) {
            uint32_t afr[2][4];
#pragma unroll
            for (int mi = 0; mi < 2; mi++) {
                int ra = mi * 16 + gid;
                afr[mi][0] = tss[ra * LDA_TS + k0 + tid4];
                afr[mi][1] = tss[(ra + 8) * LDA_TS + k0 + tid4];
                afr[mi][2] = tss[ra * LDA_TS + k0 + tid4 + 4];
                afr[mi][3] = tss[(ra + 8) * LDA_TS + k0 + tid4 + 4];
            }
#pragma unroll
            for (int ni = 0; ni < 4; ni++) {
                int nn = n0c + ni * 8 + gid;
                uint32_t bf0 = W2s[(k0 + tid4) * LDW + nn];
                uint32_t bf1 = W2s[(k0 + tid4 + 4) * LDW + nn];
                mma_tf32(acc[0][ni], afr[0], bf0, bf1);
                mma_tf32(acc[1][ni], afr[1], bf0, bf1);
            }
        }
        gbar(bid);  // stage-2 reads of tss done

        // Stage results*C back into tss (fp32)
#pragma unroll
        for (int mi = 0; mi < 2; mi++) {
            int rA = mi * 16 + gid;
            int rB = rA + 8;
            float CA = Cs[rA], CB = Cs[rB];
#pragma unroll
            for (int ni = 0; ni < 4; ni++) {
                int col = n0c + ni * 8 + 2 * tid4;
                *(float2*)(tssf + rA * LDA_TS + col) =
                    make_float2(acc[mi][ni][0] * CA, acc[mi][ni][1] * CA);
                *(float2*)(tssf + rB * LDA_TS + col) =
                    make_float2(acc[mi][ni][2] * CB, acc[mi][ni][3] * CB);
            }
        }
        gbar(bid);

        // ---- Coalesced epilogue: one warp covers one edge row per step ----
#pragma unroll
        for (int it = 0; it < 8; it++) {
            int idx = it * 128 + tg;
            int r = idx >> 5, c4 = idx & 31;
            float4 w4v = *(const float4*)(tssf + r * LDA_TS + c4 * 4);
            const float* hrow = g_h + (size_t)ss[r] * 128 + c4 * 4;
            float4 h4 = *(const float4*)hrow;
            float* arow = g_agg + (size_t)ds[r] * 128 + c4 * 4;
            red4(arow, w4v.x * h4.x, w4v.y * h4.y, w4v.z * h4.z, w4v.w * h4.w);
        }
    }
}

__global__ void zero_kernel(float4* p, int n4) {
    int i = blockIdx.x * blockDim.x + threadIdx.x;
    if (i < n4) p[i] = make_float4(0.f, 0.f, 0.f, 0.f);
}

extern "C" void kernel_launch(void* const* d_in, const int* in_sizes, int n_in,
                              void* d_out, int out_size) {
    const float* x = (const float*)d_in[0];
    const int* eidx = (const int*)d_in[1];
    const float* elen = (const float*)d_in[2];
    const float* eattr = (const float*)d_in[3];
    const float* lin1_w = (const float*)d_in[4];
    const float* nn_w1 = (const float*)d_in[5];
    const float* nn_b1 = (const float*)d_in[6];
    const float* nn_w2 = (const float*)d_in[7];
    const float* nn_b2 = (const float*)d_in[8];
    const float* lin2_w = (const float*)d_in[9];
    const float* lin2_b = (const float*)d_in[10];
    const float* lin_w = (const float*)d_in[11];
    const float* lin_b = (const float*)d_in[12];
    float* out = (float*)d_out;

    float *h_p, *agg_p, *tmp_p;
    cudaGetSymbolAddress((void**)&h_p, g_h);
    cudaGetSymbolAddress((void**)&agg_p, g_agg);
    cudaGetSymbolAddress((void**)&tmp_p, g_tmp);

    const size_t ngemm_smem =
        (size_t)(128 * LDA_TS + 128 * LDW) * 4 + 128 * sizeof(float);
    const size_t edge_smem =
        (size_t)(64 * LDW + 128 * LDW + 4 * TEDGE * LDA_EA +
                 4 * TEDGE * LDA_TS) *
            4 +
        (size_t)(2 * 128 + 4 * TEDGE) * sizeof(float) +
        (size_t)(8 * TEDGE) * sizeof(int);

    cudaFuncSetAttribute(gemm128_tf32_kernel<0, 0>,
                         cudaFuncAttributeMaxDynamicSharedMemorySize,
                         (int)ngemm_smem);
    cudaFuncSetAttribute(gemm128_tf32_kernel<1, 1>,
                         cudaFuncAttributeMaxDynamicSharedMemorySize,
                         (int)ngemm_smem);
    cudaFuncSetAttribute(gemm128_tf32_kernel<0, 1>,
                         cudaFuncAttributeMaxDynamicSharedMemorySize,
                         (int)ngemm_smem);
    cudaFuncSetAttribute(edge_fused_kernel,
                         cudaFuncAttributeMaxDynamicSharedMemorySize,
                         (int)edge_smem);

    const int gridN = (N_NODES + 127) / 128;  // 391

    gemm128_tf32_kernel<0, 0><<<gridN, 512, ngemm_smem>>>(x, lin1_w, nullptr,
                                                          h_p, N_NODES);
    {
        int n4 = N_NODES * NFEAT / 4;
        zero_kernel<<<(n4 + 255) / 256, 256>>>((float4*)agg_p, n4);
    }
    edge_fused_kernel<<<148, 512, edge_smem>>>(eattr, eidx, elen, nn_w1, nn_b1,
                                               nn_w2, nn_b2);
    gemm128_tf32_kernel<1, 1><<<gridN, 512, ngemm_smem>>>(agg_p, lin2_w,
                                                          lin2_b, tmp_p,
                                                          N_NODES);
    gemm128_tf32_kernel<0, 1><<<gridN, 512, ngemm_smem>>>(tmp_p, lin_w, lin_b,
                                                          out, N_NODES);
}